// round 11
// baseline (speedup 1.0000x reference)
#include <cuda_runtime.h>
#include <cuda_fp16.h>
#include <math.h>
#include <stdint.h>

// Problem constants (RG_LRU: B=4, T=8192, D=1024, C=8)
#define B_ 4
#define T_ 8192
#define D_ 1024
#define M_ (B_ * T_)          // 32768 rows

// Chunked scan: chunk == GEMM row tile (128 consecutive timesteps)
#define TCHUNK 128
#define NCHK_PER_B (T_ / TCHUNK)      // 64
#define NCHUNKS (M_ / TCHUNK)         // 256

// GEMM tiling
#define BM 128
#define BN 64
#define BK 32                 // fp16 per K-tile = 64 B rows (SW64 atom)
#define KT (D_ / BK)          // 32

// smem stage layout (bytes): x tile 128x64B = 8KB, W tiles 64x64B = 4KB each
#define OFF_X   0
#define OFF_WI  8192
#define OFF_WG  12288
#define STAGE_SZ 16384
#define NSTAGE 5              // 80 KB pipeline

// epilogue scan arrays (union with pipeline stages)
#define AL_STRIDE 66                     // padded row stride (floats)
#define AL_OFF  0                        // alpha  [128][66] = 33792 B
#define XB_OFF  33792                    // xbeta  [128][66] = 33792 B
#define AGG_OFF 67584                    // seg aggregates: 2 x 256 floats
#define PAR_OFF (NSTAGE * STAGE_SZ)      // 81920
#define SMEM_DYN (PAR_OFF + 768 + 1024)  // ~83.6 KB -> 2 CTAs/SM

// ---------------- device scratch (allocation-free) ----------------
// Packed prefix pairs: h_t = P_t * carry + S_t,  stored as half2(P, S)
__device__ __half2 g_PS[(size_t)M_ * D_];    // 128 MB
__device__ float g_Ac[(size_t)NCHUNKS * D_]; // chunk aggregate products (fp32)
__device__ float g_Bc[(size_t)NCHUNKS * D_]; // chunk aggregate scan values (fp32)
__device__ float g_carry[(size_t)NCHUNKS * D_];
__device__ __half g_xh[(size_t)M_ * D_];     // 64 MB
__device__ __half g_wi[D_ * D_];             // 2 MB
__device__ __half g_wg[D_ * D_];             // 2 MB

// ---------------- helpers ----------------
__device__ __forceinline__ uint32_t smem_u32(const void* p) {
    uint32_t a;
    asm("{ .reg .u64 t; cvta.to.shared.u64 t, %1; cvt.u32.u64 %0, t; }" : "=r"(a) : "l"(p));
    return a;
}
__device__ __forceinline__ void cp16(uint32_t dst, const void* src) {
    asm volatile("cp.async.cg.shared.global [%0], [%1], 16;" :: "r"(dst), "l"(src));
}
#define CP_COMMIT() asm volatile("cp.async.commit_group;" ::: "memory")
#define CP_WAIT(n)  asm volatile("cp.async.wait_group %0;" :: "n"(n) : "memory")

__device__ __forceinline__ void ldsm4(uint32_t addr, uint32_t& r0, uint32_t& r1,
                                      uint32_t& r2, uint32_t& r3) {
    asm volatile("ldmatrix.sync.aligned.m8n8.x4.shared.b16 {%0,%1,%2,%3}, [%4];"
                 : "=r"(r0), "=r"(r1), "=r"(r2), "=r"(r3) : "r"(addr));
}
__device__ __forceinline__ void mma16816(float* d, const uint32_t* a, const uint32_t* b) {
    asm volatile("mma.sync.aligned.m16n8k16.row.col.f32.f16.f16.f32 "
                 "{%0,%1,%2,%3}, {%4,%5,%6,%7}, {%8,%9}, {%0,%1,%2,%3};"
                 : "+f"(d[0]), "+f"(d[1]), "+f"(d[2]), "+f"(d[3])
                 : "r"(a[0]), "r"(a[1]), "r"(a[2]), "r"(a[3]), "r"(b[0]), "r"(b[1]));
}
__device__ __forceinline__ float sigm(float v) { return 1.0f / (1.0f + __expf(-v)); }

// SW64 swizzle for 64B rows: chunk c (16B) at row r -> c ^ ((r>>1)&3)
__device__ __forceinline__ uint32_t sw64_off(int r, int c) {
    return (uint32_t)(r * 64 + ((c ^ ((r >> 1) & 3)) << 4));
}

// ---------------- fp32 -> fp16 conversion kernels ----------------
__global__ void __launch_bounds__(256)
conv_x(const float* __restrict__ x)
{
    size_t i = (size_t)blockIdx.x * 256 + threadIdx.x;   // float4 index
    float4 v = ((const float4*)x)[i];
    ushort4 h;
    h.x = __half_as_ushort(__float2half(v.x));
    h.y = __half_as_ushort(__float2half(v.y));
    h.z = __half_as_ushort(__float2half(v.z));
    h.w = __half_as_ushort(__float2half(v.w));
    ((ushort4*)g_xh)[i] = h;
}

__global__ void __launch_bounds__(256)
conv_w(const float* __restrict__ wi, const float* __restrict__ wg)
{
    size_t i = (size_t)blockIdx.x * 256 + threadIdx.x;
    float4 a = ((const float4*)wi)[i];
    float4 b = ((const float4*)wg)[i];
    ushort4 h;
    h.x = __half_as_ushort(__float2half(a.x));
    h.y = __half_as_ushort(__float2half(a.y));
    h.z = __half_as_ushort(__float2half(a.z));
    h.w = __half_as_ushort(__float2half(a.w));
    ((ushort4*)g_wi)[i] = h;
    h.x = __half_as_ushort(__float2half(b.x));
    h.y = __half_as_ushort(__float2half(b.y));
    h.z = __half_as_ushort(__float2half(b.z));
    h.w = __half_as_ushort(__float2half(b.w));
    ((ushort4*)g_wg)[i] = h;
}

// ---------------- stage loader: gmem -> SW64-swizzled smem ----------------
__device__ __forceinline__ void ld_stage(uint32_t sbase, int kt, int m0, int n0, int tid)
{
    const int k0 = kt * BK;
#pragma unroll
    for (int i = 0; i < 2; i++) {            // x tile: 128 rows x 4 chunks
        int q = tid + i * 256;
        int r = q >> 2, c = q & 3;
        uint32_t off = sw64_off(r, c);
        size_t gi = (size_t)(m0 + r) * D_ + k0 + c * 8;
        cp16(sbase + OFF_X + off, g_xh + gi);
    }
    {                                        // W tiles: 64 rows x 4 chunks
        int q = tid;
        int r = q >> 2, c = q & 3;
        uint32_t off = sw64_off(r, c);
        size_t gi = (size_t)(n0 + r) * D_ + k0 + c * 8;
        cp16(sbase + OFF_WI + off, g_wi + gi);
        cp16(sbase + OFF_WG + off, g_wg + gi);
    }
}

// ---- fused dual-GEMM (HMMA fp16) + gate epilogue + intra-chunk prefix scan ----
// Single-barrier pipeline: at iteration kt, wait for stage kt, one __syncthreads,
// then load stage kt+NSTAGE-1 into slot (kt-1)%NSTAGE (consumed last iteration;
// the barrier proves all warps finished reading it). cp.asyncs overlap the MMAs.
__global__ void __launch_bounds__(256, 2)
gates_gemm_hmma(const float* __restrict__ x,
                const float* __restrict__ bin, const float* __restrict__ bgt,
                const float* __restrict__ lam)
{
    extern __shared__ char smem_raw[];
    char* smem = (char*)(((uintptr_t)smem_raw + 1023) & ~(uintptr_t)1023);
    const uint32_t sb = smem_u32(smem);
    const int tid = threadIdx.x;
    const int lane = tid & 31;
    const int wid = tid >> 5;
    const int wm = wid >> 1;                 // 0..3
    const int wn = wid & 1;                  // 0..1
    const int m0 = blockIdx.y * BM;          // chunk start row
    const int n0 = blockIdx.x * BN;

    float* cl_s = (float*)(smem + PAR_OFF);
    float* bi_s = cl_s + 64;
    float* bg_s = bi_s + 64;
    if (tid < 64) {
        float l = lam[n0 + tid];
        cl_s[tid] = 8.0f * log1pf(expf(l));  // C * softplus(lambda)
        bi_s[tid] = bin[n0 + tid];
        bg_s[tid] = bgt[n0 + tid];
    }

    float aig[2][4][4], arg[2][4][4];
#pragma unroll
    for (int mb = 0; mb < 2; mb++)
#pragma unroll
        for (int nb = 0; nb < 4; nb++)
#pragma unroll
            for (int q = 0; q < 4; q++) { aig[mb][nb][q] = 0.f; arg[mb][nb][q] = 0.f; }

    const int r16 = (lane & 7) | (((lane >> 3) & 1) << 3);  // row within 16
    const int coff = lane >> 4;                             // k-chunk offset 0/1
    int arow[2], brow[2];
#pragma unroll
    for (int mb = 0; mb < 2; mb++) arow[mb] = wm * 32 + mb * 16 + r16;
#pragma unroll
    for (int j = 0; j < 2; j++)    brow[j] = wn * 32 + j * 16 + r16;

    // prologue: fill NSTAGE-1 stages
#pragma unroll
    for (int s = 0; s < NSTAGE - 1; s++) { ld_stage(sb + s * STAGE_SZ, s, m0, n0, tid); CP_COMMIT(); }

    for (int kt = 0; kt < KT; kt++) {
        CP_WAIT(NSTAGE - 2);                 // stage kt landed
        __syncthreads();                     // visible to all; slot (kt-1)%NSTAGE free

        const int nk = kt + NSTAGE - 1;
        if (nk < KT) ld_stage(sb + (nk % NSTAGE) * STAGE_SZ, nk, m0, n0, tid);
        CP_COMMIT();                         // commit every iteration (possibly empty)

        const uint32_t stb = sb + (kt % NSTAGE) * STAGE_SZ;
#pragma unroll
        for (int k16 = 0; k16 < 2; k16++) {
            const int chunk = k16 * 2 + coff;
            uint32_t ax[2][4];
#pragma unroll
            for (int mb = 0; mb < 2; mb++) {
                uint32_t off = sw64_off(arow[mb], chunk);
                ldsm4(stb + OFF_X + off, ax[mb][0], ax[mb][1], ax[mb][2], ax[mb][3]);
            }
            uint32_t bwi[4][2], bwg[4][2];
#pragma unroll
            for (int j = 0; j < 2; j++) {
                uint32_t off = sw64_off(brow[j], chunk);
                uint32_t r0, r1, r2, r3;
                ldsm4(stb + OFF_WI + off, r0, r1, r2, r3);
                bwi[j * 2 + 0][0] = r0; bwi[j * 2 + 0][1] = r2;
                bwi[j * 2 + 1][0] = r1; bwi[j * 2 + 1][1] = r3;
                ldsm4(stb + OFF_WG + off, r0, r1, r2, r3);
                bwg[j * 2 + 0][0] = r0; bwg[j * 2 + 0][1] = r2;
                bwg[j * 2 + 1][0] = r1; bwg[j * 2 + 1][1] = r3;
            }
#pragma unroll
            for (int mb = 0; mb < 2; mb++)
#pragma unroll
                for (int nb = 0; nb < 4; nb++)
                    mma16816(aig[mb][nb], ax[mb], bwi[nb]);
#pragma unroll
            for (int mb = 0; mb < 2; mb++)
#pragma unroll
                for (int nb = 0; nb < 4; nb++)
                    mma16816(arg[mb][nb], ax[mb], bwg[nb]);
        }
    }
    __syncthreads();    // all warps done with stage smem before epilogue reuses it

    // -------- epilogue 1: gate math -> smem (reusing dead stage memory) --------
    float* al_s = (float*)(smem + AL_OFF);   // [128][AL_STRIDE]
    float* xb_s = (float*)(smem + XB_OFF);
    const int g = lane >> 2;
    const int t2 = 2 * (lane & 3);
#pragma unroll
    for (int mb = 0; mb < 2; mb++) {
#pragma unroll
        for (int half = 0; half < 2; half++) {
            const int rl = wm * 32 + mb * 16 + g + half * 8;   // 0..127
#pragma unroll
            for (int nb = 0; nb < 4; nb++) {
                const int cloc = wn * 32 + nb * 8 + t2;        // 0..63
                const size_t gi = (size_t)(m0 + rl) * D_ + n0 + cloc;
                float2 xv = *(const float2*)(x + gi);
                float a2[2], v2[2];
#pragma unroll
                for (int q = 0; q < 2; q++) {
                    float ig = aig[mb][nb][half * 2 + q] + bi_s[cloc + q];
                    float rg = arg[mb][nb][half * 2 + q] + bg_s[cloc + q];
                    float sr = sigm(rg);
                    float al = __expf(-cl_s[cloc + q] * sr);
                    float be = sqrtf(fmaxf(1.0f - al * al + 1e-6f, 0.0f));
                    a2[q] = al;
                    v2[q] = be * sigm(ig) * ((q == 0) ? xv.x : xv.y);
                }
                *(float2*)(al_s + rl * AL_STRIDE + cloc) = make_float2(a2[0], a2[1]);
                *(float2*)(xb_s + rl * AL_STRIDE + cloc) = make_float2(v2[0], v2[1]);
            }
        }
    }
    __syncthreads();

    // -------- epilogue 2: intra-chunk prefix scan (h_t = P_t*carry + S_t) --------
    const int seg = tid >> 6;        // 4 segments of 32 timesteps
    const int ch  = tid & 63;        // channel within tile
    float P = 1.f, S = 0.f;
#pragma unroll 8
    for (int s = 0; s < 32; s++) {
        float a = al_s[(seg * 32 + s) * AL_STRIDE + ch];
        float v = xb_s[(seg * 32 + s) * AL_STRIDE + ch];
        S = fmaf(a, S, v);
        P *= a;
    }
    float* aggP = (float*)(smem + AGG_OFF);
    float* aggS = aggP + 256;
    aggP[seg * 64 + ch] = P;
    aggS[seg * 64 + ch] = S;
    __syncthreads();
    float Pc = 1.f, Sc = 0.f;
#pragma unroll
    for (int q = 0; q < 3; q++) {
        if (q < seg) {
            float pq = aggP[q * 64 + ch], sq = aggS[q * 64 + ch];
            Sc = fmaf(pq, Sc, sq);
            Pc *= pq;
        }
    }
    P = Pc; S = Sc;
#pragma unroll 8
    for (int s = 0; s < 32; s++) {
        const int rl = seg * 32 + s;
        float a = al_s[rl * AL_STRIDE + ch];
        float v = xb_s[rl * AL_STRIDE + ch];
        P *= a;
        S = fmaf(a, S, v);
        const size_t gi = (size_t)(m0 + rl) * D_ + n0 + ch;
        g_PS[gi] = __floats2half2_rn(P, S);   // packed fp16 prefix pair
    }
    if (seg == 3) {
        const size_t ci = (size_t)blockIdx.y * D_ + n0 + ch;
        g_Ac[ci] = P;    // fp32 aggregates (carry chain stays accurate)
        g_Bc[ci] = S;
    }
}

// ------- carry scan over chunk aggregates (batched prefetch, MLP=16) -------
__global__ void __launch_bounds__(256)
scan_carry()
{
    const int b = blockIdx.x;                 // 0..3 (batch)
    const int d4 = threadIdx.x;               // 0..255 (float4 channel group)
    float4 h = make_float4(0.f, 0.f, 0.f, 0.f);
    for (int base = 0; base < NCHK_PER_B; base += 8) {
        float4 a[8], v[8];
#pragma unroll
        for (int j = 0; j < 8; j++) {
            const size_t i = (size_t)(b * NCHK_PER_B + base + j) * (D_ / 4) + d4;
            a[j] = ((const float4*)g_Ac)[i];
            v[j] = ((const float4*)g_Bc)[i];
        }
#pragma unroll
        for (int j = 0; j < 8; j++) {
            const size_t i = (size_t)(b * NCHK_PER_B + base + j) * (D_ / 4) + d4;
            ((float4*)g_carry)[i] = h;
            h.x = fmaf(a[j].x, h.x, v[j].x);
            h.y = fmaf(a[j].y, h.y, v[j].y);
            h.z = fmaf(a[j].z, h.z, v[j].z);
            h.w = fmaf(a[j].w, h.w, v[j].w);
        }
    }
}

// ---------------- elementwise apply: out = P*carry + S ----------------
__global__ void __launch_bounds__(256)
scan_apply(float* __restrict__ out)
{
    const int gid = blockIdx.x * 256 + threadIdx.x;    // 0 .. 262143
    const int cid = gid >> 10;                         // chunk 0..255
    const int seg = (gid >> 8) & 3;                    // 32-step segment
    const int d4  = gid & 255;

    const float4 c = ((const float4*)g_carry)[(size_t)cid * (D_ / 4) + d4];
    size_t fi = (size_t)(cid * TCHUNK + seg * 32) * (D_ / 4) + d4;
#pragma unroll 4
    for (int s = 0; s < 32; s++) {
        uint4 w = __ldcs((const uint4*)g_PS + fi);     // streaming read (read-once)
        float2 e0 = __half22float2(*(__half2*)&w.x);
        float2 e1 = __half22float2(*(__half2*)&w.y);
        float2 e2 = __half22float2(*(__half2*)&w.z);
        float2 e3 = __half22float2(*(__half2*)&w.w);
        float4 o;
        o.x = fmaf(e0.x, c.x, e0.y);
        o.y = fmaf(e1.x, c.y, e1.y);
        o.z = fmaf(e2.x, c.z, e2.y);
        o.w = fmaf(e3.x, c.w, e3.y);
        __stcs((float4*)out + fi, o);                  // streaming write (write-only)
        fi += D_ / 4;
    }
}

// ---------------- launch ----------------
extern "C" void kernel_launch(void* const* d_in, const int* in_sizes, int n_in,
                              void* d_out, int out_size)
{
    const float* x   = (const float*)d_in[0];
    const float* Win = (const float*)d_in[1];
    const float* bin = (const float*)d_in[2];
    const float* Wg  = (const float*)d_in[3];
    const float* bgt = (const float*)d_in[4];
    const float* lam = (const float*)d_in[5];
    float* out = (float*)d_out;

    cudaFuncSetAttribute(gates_gemm_hmma, cudaFuncAttributeMaxDynamicSharedMemorySize, SMEM_DYN);

    conv_x<<<(M_ * (D_ / 4)) / 256, 256>>>(x);
    conv_w<<<(D_ * (D_ / 4)) / 256, 256>>>(Win, Wg);

    dim3 ggrid(D_ / BN, M_ / BM);                // (16, 256)
    gates_gemm_hmma<<<ggrid, 256, SMEM_DYN>>>(x, bin, bgt, lam);

    scan_carry<<<B_, 256>>>();                   // 4 blocks
    scan_apply<<<1024, 256>>>(out);
}

// round 12
// speedup vs baseline: 1.0729x; 1.0729x over previous
#include <cuda_runtime.h>
#include <cuda_fp16.h>
#include <math.h>
#include <stdint.h>

// Problem constants (RG_LRU: B=4, T=8192, D=1024, C=8)
#define B_ 4
#define T_ 8192
#define D_ 1024
#define M_ (B_ * T_)          // 32768 rows

// Chunked scan: chunk == GEMM row tile (128 consecutive timesteps)
#define TCHUNK 128
#define NCHK_PER_B (T_ / TCHUNK)      // 64
#define NCHUNKS (M_ / TCHUNK)         // 256

// GEMM tiling
#define BM 128
#define BN 64
#define BK 32                 // fp16 per K-tile = 64 B rows (SW64 atom)
#define KT (D_ / BK)          // 32

// smem stage layout (bytes): x tile 128x64B = 8KB, W tiles 64x64B = 4KB each
#define OFF_X   0
#define OFF_WI  8192
#define OFF_WG  12288
#define STAGE_SZ 16384
#define NSTAGE 5              // 80 KB pipeline

// epilogue scan arrays (union with pipeline stages)
#define AL_STRIDE 66                     // padded row stride (floats)
#define AL_OFF  0                        // alpha  [128][66] = 33792 B
#define XB_OFF  33792                    // xbeta  [128][66] = 33792 B
#define AGG_OFF 67584                    // seg aggregates: 2 x 256 floats
#define PAR_OFF (NSTAGE * STAGE_SZ)      // 81920
#define SMEM_DYN (PAR_OFF + 768 + 1024)  // ~83.6 KB -> 2 CTAs/SM

// ---------------- device scratch (allocation-free) ----------------
// Packed prefix pairs: h_t = P_t * carry + S_t,  stored as half2(P, S)
__device__ __half2 g_PS[(size_t)M_ * D_];    // 128 MB
__device__ float g_Ac[(size_t)NCHUNKS * D_]; // chunk aggregate products (fp32)
__device__ float g_Bc[(size_t)NCHUNKS * D_]; // chunk aggregate scan values (fp32)
__device__ float g_carry[(size_t)NCHUNKS * D_];
__device__ __half g_xh[(size_t)M_ * D_];     // 64 MB
__device__ __half g_wi[D_ * D_];             // 2 MB
__device__ __half g_wg[D_ * D_];             // 2 MB

// ---------------- helpers ----------------
__device__ __forceinline__ uint32_t smem_u32(const void* p) {
    uint32_t a;
    asm("{ .reg .u64 t; cvta.to.shared.u64 t, %1; cvt.u32.u64 %0, t; }" : "=r"(a) : "l"(p));
    return a;
}
__device__ __forceinline__ void cp16(uint32_t dst, const void* src) {
    asm volatile("cp.async.cg.shared.global [%0], [%1], 16;" :: "r"(dst), "l"(src));
}
#define CP_COMMIT() asm volatile("cp.async.commit_group;" ::: "memory")
#define CP_WAIT(n)  asm volatile("cp.async.wait_group %0;" :: "n"(n) : "memory")

__device__ __forceinline__ void ldsm4(uint32_t addr, uint32_t& r0, uint32_t& r1,
                                      uint32_t& r2, uint32_t& r3) {
    asm volatile("ldmatrix.sync.aligned.m8n8.x4.shared.b16 {%0,%1,%2,%3}, [%4];"
                 : "=r"(r0), "=r"(r1), "=r"(r2), "=r"(r3) : "r"(addr));
}
__device__ __forceinline__ void mma16816(float* d, const uint32_t* a, const uint32_t* b) {
    asm volatile("mma.sync.aligned.m16n8k16.row.col.f32.f16.f16.f32 "
                 "{%0,%1,%2,%3}, {%4,%5,%6,%7}, {%8,%9}, {%0,%1,%2,%3};"
                 : "+f"(d[0]), "+f"(d[1]), "+f"(d[2]), "+f"(d[3])
                 : "r"(a[0]), "r"(a[1]), "r"(a[2]), "r"(a[3]), "r"(b[0]), "r"(b[1]));
}
__device__ __forceinline__ float sigm(float v) { return 1.0f / (1.0f + __expf(-v)); }

// SW64 swizzle for 64B rows: chunk c (16B) at row r -> c ^ ((r>>1)&3)
__device__ __forceinline__ uint32_t sw64_off(int r, int c) {
    return (uint32_t)(r * 64 + ((c ^ ((r >> 1) & 3)) << 4));
}

// ---------------- fp32 -> fp16 conversion kernels ----------------
__global__ void __launch_bounds__(256)
conv_x(const float* __restrict__ x)
{
    size_t i = (size_t)blockIdx.x * 256 + threadIdx.x;   // float4 index
    float4 v = ((const float4*)x)[i];
    ushort4 h;
    h.x = __half_as_ushort(__float2half(v.x));
    h.y = __half_as_ushort(__float2half(v.y));
    h.z = __half_as_ushort(__float2half(v.z));
    h.w = __half_as_ushort(__float2half(v.w));
    ((ushort4*)g_xh)[i] = h;
}

__global__ void __launch_bounds__(256)
conv_w(const float* __restrict__ wi, const float* __restrict__ wg)
{
    size_t i = (size_t)blockIdx.x * 256 + threadIdx.x;
    float4 a = ((const float4*)wi)[i];
    float4 b = ((const float4*)wg)[i];
    ushort4 h;
    h.x = __half_as_ushort(__float2half(a.x));
    h.y = __half_as_ushort(__float2half(a.y));
    h.z = __half_as_ushort(__float2half(a.z));
    h.w = __half_as_ushort(__float2half(a.w));
    ((ushort4*)g_wi)[i] = h;
    h.x = __half_as_ushort(__float2half(b.x));
    h.y = __half_as_ushort(__float2half(b.y));
    h.z = __half_as_ushort(__float2half(b.z));
    h.w = __half_as_ushort(__float2half(b.w));
    ((ushort4*)g_wg)[i] = h;
}

// ---------------- stage loader: gmem -> SW64-swizzled smem ----------------
__device__ __forceinline__ void ld_stage(uint32_t sbase, int kt, int m0, int n0, int tid)
{
    const int k0 = kt * BK;
#pragma unroll
    for (int i = 0; i < 2; i++) {            // x tile: 128 rows x 4 chunks
        int q = tid + i * 256;
        int r = q >> 2, c = q & 3;
        uint32_t off = sw64_off(r, c);
        size_t gi = (size_t)(m0 + r) * D_ + k0 + c * 8;
        cp16(sbase + OFF_X + off, g_xh + gi);
    }
    {                                        // W tiles: 64 rows x 4 chunks
        int q = tid;
        int r = q >> 2, c = q & 3;
        uint32_t off = sw64_off(r, c);
        size_t gi = (size_t)(n0 + r) * D_ + k0 + c * 8;
        cp16(sbase + OFF_WI + off, g_wi + gi);
        cp16(sbase + OFF_WG + off, g_wg + gi);
    }
}

// ---- fused dual-GEMM (HMMA fp16) + gate epilogue + intra-chunk prefix scan ----
__global__ void __launch_bounds__(256, 2)
gates_gemm_hmma(const float* __restrict__ x,
                const float* __restrict__ bin, const float* __restrict__ bgt,
                const float* __restrict__ lam)
{
    extern __shared__ char smem_raw[];
    char* smem = (char*)(((uintptr_t)smem_raw + 1023) & ~(uintptr_t)1023);
    const uint32_t sb = smem_u32(smem);
    const int tid = threadIdx.x;
    const int lane = tid & 31;
    const int wid = tid >> 5;
    const int wm = wid >> 1;                 // 0..3
    const int wn = wid & 1;                  // 0..1
    const int m0 = blockIdx.y * BM;          // chunk start row
    const int n0 = blockIdx.x * BN;

    float* cl_s = (float*)(smem + PAR_OFF);
    float* bi_s = cl_s + 64;
    float* bg_s = bi_s + 64;
    if (tid < 64) {
        float l = lam[n0 + tid];
        cl_s[tid] = 8.0f * log1pf(expf(l));  // C * softplus(lambda)
        bi_s[tid] = bin[n0 + tid];
        bg_s[tid] = bgt[n0 + tid];
    }

    float aig[2][4][4], arg[2][4][4];
#pragma unroll
    for (int mb = 0; mb < 2; mb++)
#pragma unroll
        for (int nb = 0; nb < 4; nb++)
#pragma unroll
            for (int q = 0; q < 4; q++) { aig[mb][nb][q] = 0.f; arg[mb][nb][q] = 0.f; }

    const int r16 = (lane & 7) | (((lane >> 3) & 1) << 3);  // row within 16
    const int coff = lane >> 4;                             // k-chunk offset 0/1
    // Precomputed loop-invariant swizzled LDSM offsets (chunk takes only 2
    // values per thread: coff and 2+coff). Kills per-iteration swizzle ALU.
    uint32_t off_x[2][2], off_w[2][2];
#pragma unroll
    for (int k16 = 0; k16 < 2; k16++) {
        const int chunk = k16 * 2 + coff;
#pragma unroll
        for (int mb = 0; mb < 2; mb++)
            off_x[k16][mb] = OFF_X + sw64_off(wm * 32 + mb * 16 + r16, chunk);
#pragma unroll
        for (int j = 0; j < 2; j++)
            off_w[k16][j] = sw64_off(wn * 32 + j * 16 + r16, chunk);
    }

    // prologue: fill pipeline
#pragma unroll
    for (int s = 0; s < NSTAGE; s++) { ld_stage(sb + s * STAGE_SZ, s, m0, n0, tid); CP_COMMIT(); }

    for (int kt = 0; kt < KT; kt++) {
        const uint32_t stb = sb + (kt % NSTAGE) * STAGE_SZ;
        CP_WAIT(NSTAGE - 1);
        __syncthreads();

#pragma unroll
        for (int k16 = 0; k16 < 2; k16++) {
            uint32_t ax[2][4];
#pragma unroll
            for (int mb = 0; mb < 2; mb++)
                ldsm4(stb + off_x[k16][mb], ax[mb][0], ax[mb][1], ax[mb][2], ax[mb][3]);
            uint32_t bwi[4][2], bwg[4][2];
#pragma unroll
            for (int j = 0; j < 2; j++) {
                const uint32_t off = off_w[k16][j];
                uint32_t r0, r1, r2, r3;
                ldsm4(stb + OFF_WI + off, r0, r1, r2, r3);
                bwi[j * 2 + 0][0] = r0; bwi[j * 2 + 0][1] = r2;
                bwi[j * 2 + 1][0] = r1; bwi[j * 2 + 1][1] = r3;
                ldsm4(stb + OFF_WG + off, r0, r1, r2, r3);
                bwg[j * 2 + 0][0] = r0; bwg[j * 2 + 0][1] = r2;
                bwg[j * 2 + 1][0] = r1; bwg[j * 2 + 1][1] = r3;
            }
#pragma unroll
            for (int mb = 0; mb < 2; mb++)
#pragma unroll
                for (int nb = 0; nb < 4; nb++)
                    mma16816(aig[mb][nb], ax[mb], bwi[nb]);
#pragma unroll
            for (int mb = 0; mb < 2; mb++)
#pragma unroll
                for (int nb = 0; nb < 4; nb++)
                    mma16816(arg[mb][nb], ax[mb], bwg[nb]);
        }
        __syncthreads();
        // Always commit a group (possibly empty) so wait_group(NSTAGE-1)
        // always guarantees the consumed stage has landed.
        const int nk = kt + NSTAGE;
        if (nk < KT) ld_stage(stb, nk, m0, n0, tid);
        CP_COMMIT();
    }

    // -------- epilogue 1: gate math -> smem (reusing dead stage memory) --------
    float* al_s = (float*)(smem + AL_OFF);   // [128][AL_STRIDE]
    float* xb_s = (float*)(smem + XB_OFF);
    const int g = lane >> 2;
    const int t2 = 2 * (lane & 3);
#pragma unroll
    for (int mb = 0; mb < 2; mb++) {
#pragma unroll
        for (int half = 0; half < 2; half++) {
            const int rl = wm * 32 + mb * 16 + g + half * 8;   // 0..127
#pragma unroll
            for (int nb = 0; nb < 4; nb++) {
                const int cloc = wn * 32 + nb * 8 + t2;        // 0..63
                const size_t gi = (size_t)(m0 + rl) * D_ + n0 + cloc;
                float2 xv = *(const float2*)(x + gi);
                float a2[2], v2[2];
#pragma unroll
                for (int q = 0; q < 2; q++) {
                    float ig = aig[mb][nb][half * 2 + q] + bi_s[cloc + q];
                    float rg = arg[mb][nb][half * 2 + q] + bg_s[cloc + q];
                    float sr = sigm(rg);
                    float al = __expf(-cl_s[cloc + q] * sr);
                    float be = sqrtf(fmaxf(1.0f - al * al + 1e-6f, 0.0f));
                    a2[q] = al;
                    v2[q] = be * sigm(ig) * ((q == 0) ? xv.x : xv.y);
                }
                *(float2*)(al_s + rl * AL_STRIDE + cloc) = make_float2(a2[0], a2[1]);
                *(float2*)(xb_s + rl * AL_STRIDE + cloc) = make_float2(v2[0], v2[1]);
            }
        }
    }
    __syncthreads();

    // -------- epilogue 2: intra-chunk prefix scan (h_t = P_t*carry + S_t) --------
    const int seg = tid >> 6;        // 4 segments of 32 timesteps
    const int ch  = tid & 63;        // channel within tile
    float P = 1.f, S = 0.f;
#pragma unroll 8
    for (int s = 0; s < 32; s++) {
        float a = al_s[(seg * 32 + s) * AL_STRIDE + ch];
        float v = xb_s[(seg * 32 + s) * AL_STRIDE + ch];
        S = fmaf(a, S, v);
        P *= a;
    }
    float* aggP = (float*)(smem + AGG_OFF);
    float* aggS = aggP + 256;
    aggP[seg * 64 + ch] = P;
    aggS[seg * 64 + ch] = S;
    __syncthreads();
    float Pc = 1.f, Sc = 0.f;
#pragma unroll
    for (int q = 0; q < 3; q++) {
        if (q < seg) {
            float pq = aggP[q * 64 + ch], sq = aggS[q * 64 + ch];
            Sc = fmaf(pq, Sc, sq);
            Pc *= pq;
        }
    }
    P = Pc; S = Sc;
#pragma unroll 8
    for (int s = 0; s < 32; s++) {
        const int rl = seg * 32 + s;
        float a = al_s[rl * AL_STRIDE + ch];
        float v = xb_s[rl * AL_STRIDE + ch];
        P *= a;
        S = fmaf(a, S, v);
        const size_t gi = (size_t)(m0 + rl) * D_ + n0 + ch;
        g_PS[gi] = __floats2half2_rn(P, S);   // packed fp16 prefix pair
    }
    if (seg == 3) {
        const size_t ci = (size_t)blockIdx.y * D_ + n0 + ch;
        g_Ac[ci] = P;    // fp32 aggregates (carry chain stays accurate)
        g_Bc[ci] = S;
    }
}

// ------- carry scan over chunk aggregates (batched prefetch, MLP=16) -------
__global__ void __launch_bounds__(256)
scan_carry()
{
    const int b = blockIdx.x;                 // 0..3 (batch)
    const int d4 = threadIdx.x;               // 0..255 (float4 channel group)
    float4 h = make_float4(0.f, 0.f, 0.f, 0.f);
    for (int base = 0; base < NCHK_PER_B; base += 8) {
        float4 a[8], v[8];
#pragma unroll
        for (int j = 0; j < 8; j++) {
            const size_t i = (size_t)(b * NCHK_PER_B + base + j) * (D_ / 4) + d4;
            a[j] = ((const float4*)g_Ac)[i];
            v[j] = ((const float4*)g_Bc)[i];
        }
#pragma unroll
        for (int j = 0; j < 8; j++) {
            const size_t i = (size_t)(b * NCHK_PER_B + base + j) * (D_ / 4) + d4;
            ((float4*)g_carry)[i] = h;
            h.x = fmaf(a[j].x, h.x, v[j].x);
            h.y = fmaf(a[j].y, h.y, v[j].y);
            h.z = fmaf(a[j].z, h.z, v[j].z);
            h.w = fmaf(a[j].w, h.w, v[j].w);
        }
    }
}

// ---------------- elementwise apply: out = P*carry + S ----------------
__global__ void __launch_bounds__(256)
scan_apply(float* __restrict__ out)
{
    const int gid = blockIdx.x * 256 + threadIdx.x;    // 0 .. 262143
    const int cid = gid >> 10;                         // chunk 0..255
    const int seg = (gid >> 8) & 3;                    // 32-step segment
    const int d4  = gid & 255;

    const float4 c = ((const float4*)g_carry)[(size_t)cid * (D_ / 4) + d4];
    size_t fi = (size_t)(cid * TCHUNK + seg * 32) * (D_ / 4) + d4;
#pragma unroll 4
    for (int s = 0; s < 32; s++) {
        uint4 w = __ldcs((const uint4*)g_PS + fi);     // streaming read (read-once)
        float2 e0 = __half22float2(*(__half2*)&w.x);
        float2 e1 = __half22float2(*(__half2*)&w.y);
        float2 e2 = __half22float2(*(__half2*)&w.z);
        float2 e3 = __half22float2(*(__half2*)&w.w);
        float4 o;
        o.x = fmaf(e0.x, c.x, e0.y);
        o.y = fmaf(e1.x, c.y, e1.y);
        o.z = fmaf(e2.x, c.z, e2.y);
        o.w = fmaf(e3.x, c.w, e3.y);
        __stcs((float4*)out + fi, o);                  // streaming write (write-only)
        fi += D_ / 4;
    }
}

// ---------------- launch ----------------
extern "C" void kernel_launch(void* const* d_in, const int* in_sizes, int n_in,
                              void* d_out, int out_size)
{
    const float* x   = (const float*)d_in[0];
    const float* Win = (const float*)d_in[1];
    const float* bin = (const float*)d_in[2];
    const float* Wg  = (const float*)d_in[3];
    const float* bgt = (const float*)d_in[4];
    const float* lam = (const float*)d_in[5];
    float* out = (float*)d_out;

    cudaFuncSetAttribute(gates_gemm_hmma, cudaFuncAttributeMaxDynamicSharedMemorySize, SMEM_DYN);

    conv_x<<<(M_ * (D_ / 4)) / 256, 256>>>(x);
    conv_w<<<(D_ * (D_ / 4)) / 256, 256>>>(Win, Wg);

    dim3 ggrid(D_ / BN, M_ / BM);                // (16, 256)
    gates_gemm_hmma<<<ggrid, 256, SMEM_DYN>>>(x, bin, bgt, lam);

    scan_carry<<<B_, 256>>>();                   // 4 blocks
    scan_apply<<<1024, 256>>>(out);
}